// round 2
// baseline (speedup 1.0000x reference)
#include <cuda_runtime.h>
#include <math.h>

#define BATCH   8192
#define IN_DIM  2048
#define OUT_DIM 2048
#define DEPTH   5

#define BM 128
#define BN 128
#define BK 16
#define NT 256

// Combined additive epilogue vector: bias[o] + hd[o]
__device__ float g_add[OUT_DIM];

// hd[o] = (prod_d cos(hd_w[d,o,0]))^2 / IN_DIM
// (the circulant scan collapses: s0 is constant along axis 1, so the roll
//  terms cancel and each step just multiplies by cos(angle); phases are
//  unit-magnitude and vanish under |.|^2)
__global__ void hd_bias_kernel(const float* __restrict__ hdw,
                               const float* __restrict__ bias) {
    int o = blockIdx.x * blockDim.x + threadIdx.x;
    if (o < OUT_DIM) {
        float p = 1.0f;
#pragma unroll
        for (int d = 0; d < DEPTH; ++d) {
            p *= cosf(hdw[(size_t)d * IN_DIM * OUT_DIM + (size_t)o * OUT_DIM]);
        }
        g_add[o] = bias[o] + p * p * (1.0f / (float)IN_DIM);
    }
}

// FP32 GEMM: C[8192,2048] = tanh(A[8192,2048] @ B[2048,2048] + g_add)
// 128x128x16 tiles, 256 threads, 8x8 per thread (split-4 layout),
// double-buffered smem with register prefetch.
__global__ __launch_bounds__(NT, 2)
void gemm_tanh_kernel(const float* __restrict__ A,
                      const float* __restrict__ B,
                      float* __restrict__ C) {
    __shared__ __align__(16) float As[2][BK][BM];
    __shared__ __align__(16) float Bs[2][BK][BN];

    const int tid = threadIdx.x;
    const int tx = tid & 15;   // n-dim thread coord (0..15)
    const int ty = tid >> 4;   // m-dim thread coord (0..15)
    const int m0 = blockIdx.y * BM;
    const int n0 = blockIdx.x * BN;

    // Global-load assignments
    const int aRow = tid >> 2;         // 0..63
    const int aCol = (tid & 3) << 2;   // 0,4,8,12
    const int bRow = tid >> 5;         // 0..7
    const int bCol = (tid & 31) << 2;  // 0..124

    const float* Ap = A + (size_t)m0 * IN_DIM;
    const float* Bp = B + n0;

    float acc[8][8];
#pragma unroll
    for (int i = 0; i < 8; ++i)
#pragma unroll
        for (int j = 0; j < 8; ++j) acc[i][j] = 0.0f;

    // ---- load tile 0 into buffer 0 ----
    {
        float4 a0 = *(const float4*)(Ap + (size_t)aRow * IN_DIM + aCol);
        float4 a1 = *(const float4*)(Ap + (size_t)(aRow + 64) * IN_DIM + aCol);
        float4 b0 = *(const float4*)(Bp + (size_t)bRow * OUT_DIM + bCol);
        float4 b1 = *(const float4*)(Bp + (size_t)(bRow + 8) * OUT_DIM + bCol);

        As[0][aCol + 0][aRow] = a0.x;
        As[0][aCol + 1][aRow] = a0.y;
        As[0][aCol + 2][aRow] = a0.z;
        As[0][aCol + 3][aRow] = a0.w;
        As[0][aCol + 0][aRow + 64] = a1.x;
        As[0][aCol + 1][aRow + 64] = a1.y;
        As[0][aCol + 2][aRow + 64] = a1.z;
        As[0][aCol + 3][aRow + 64] = a1.w;
        *(float4*)&Bs[0][bRow][bCol] = b0;
        *(float4*)&Bs[0][bRow + 8][bCol] = b1;
    }
    __syncthreads();

    const int NTILES = IN_DIM / BK;  // 128
    int buf = 0;
    for (int t = 0; t < NTILES; ++t) {
        // prefetch next tile into registers (latency hidden behind FFMAs)
        float4 na0, na1, nb0, nb1;
        const bool has_next = (t + 1 < NTILES);
        if (has_next) {
            const int k0 = (t + 1) * BK;
            na0 = *(const float4*)(Ap + (size_t)aRow * IN_DIM + k0 + aCol);
            na1 = *(const float4*)(Ap + (size_t)(aRow + 64) * IN_DIM + k0 + aCol);
            nb0 = *(const float4*)(Bp + (size_t)(k0 + bRow) * OUT_DIM + bCol);
            nb1 = *(const float4*)(Bp + (size_t)(k0 + bRow + 8) * OUT_DIM + bCol);
        }

#pragma unroll
        for (int kk = 0; kk < BK; ++kk) {
            float4 ar0 = *(const float4*)&As[buf][kk][ty * 4];
            float4 ar1 = *(const float4*)&As[buf][kk][64 + ty * 4];
            float4 br0 = *(const float4*)&Bs[buf][kk][tx * 4];
            float4 br1 = *(const float4*)&Bs[buf][kk][64 + tx * 4];
            float ar[8] = {ar0.x, ar0.y, ar0.z, ar0.w, ar1.x, ar1.y, ar1.z, ar1.w};
            float br[8] = {br0.x, br0.y, br0.z, br0.w, br1.x, br1.y, br1.z, br1.w};
#pragma unroll
            for (int i = 0; i < 8; ++i)
#pragma unroll
                for (int j = 0; j < 8; ++j)
                    acc[i][j] += ar[i] * br[j];
        }

        if (has_next) {
            const int nb = buf ^ 1;
            As[nb][aCol + 0][aRow] = na0.x;
            As[nb][aCol + 1][aRow] = na0.y;
            As[nb][aCol + 2][aRow] = na0.z;
            As[nb][aCol + 3][aRow] = na0.w;
            As[nb][aCol + 0][aRow + 64] = na1.x;
            As[nb][aCol + 1][aRow + 64] = na1.y;
            As[nb][aCol + 2][aRow + 64] = na1.z;
            As[nb][aCol + 3][aRow + 64] = na1.w;
            *(float4*)&Bs[nb][bRow][bCol] = nb0;
            *(float4*)&Bs[nb][bRow + 8][bCol] = nb1;
            __syncthreads();
            buf = nb;
        }
    }

    // ---- epilogue: out = tanh(acc + bias + hd) ----
    float addv[8];
#pragma unroll
    for (int j = 0; j < 4; ++j) {
        addv[j]     = g_add[n0 + tx * 4 + j];
        addv[4 + j] = g_add[n0 + 64 + tx * 4 + j];
    }
#pragma unroll
    for (int i = 0; i < 8; ++i) {
        const int mrow = m0 + ((i < 4) ? (ty * 4 + i) : (64 + ty * 4 + (i - 4)));
        float4 o0, o1;
        o0.x = tanhf(acc[i][0] + addv[0]);
        o0.y = tanhf(acc[i][1] + addv[1]);
        o0.z = tanhf(acc[i][2] + addv[2]);
        o0.w = tanhf(acc[i][3] + addv[3]);
        o1.x = tanhf(acc[i][4] + addv[4]);
        o1.y = tanhf(acc[i][5] + addv[5]);
        o1.z = tanhf(acc[i][6] + addv[6]);
        o1.w = tanhf(acc[i][7] + addv[7]);
        *(float4*)(C + (size_t)mrow * OUT_DIM + n0 + tx * 4)      = o0;
        *(float4*)(C + (size_t)mrow * OUT_DIM + n0 + 64 + tx * 4) = o1;
    }
}

extern "C" void kernel_launch(void* const* d_in, const int* in_sizes, int n_in,
                              void* d_out, int out_size) {
    const float* x   = (const float*)d_in[0];  // [8192, 2048]
    const float* hdw = (const float*)d_in[1];  // [5, 2048, 2048]
    const float* W   = (const float*)d_in[2];  // [2048, 2048]
    const float* b   = (const float*)d_in[3];  // [2048]
    float* out = (float*)d_out;                // [8192, 2048]

    hd_bias_kernel<<<(OUT_DIM + 255) / 256, 256>>>(hdw, b);

    dim3 grid(OUT_DIM / BN, BATCH / BM);
    gemm_tanh_kernel<<<grid, NT>>>(x, W, out);
}

// round 5
// speedup vs baseline: 1.9456x; 1.9456x over previous
#include <cuda_runtime.h>
#include <cuda_bf16.h>
#include <stdint.h>

#define BATCH   8192
#define IN_DIM  2048
#define OUT_DIM 2048
#define DEPTH   5

// ---------------- device scratch (no allocs allowed) ----------------
__device__ __nv_bfloat16 g_A2[(size_t)2 * BATCH * IN_DIM];    // rows 0..8191 = hi(x), 8192.. = lo(x)
__device__ __nv_bfloat16 g_W2[(size_t)2 * OUT_DIM * IN_DIM];  // rows n = hi(W^T), 2048+n = lo(W^T)
__device__ float g_add[OUT_DIM];                              // bias + hd

// ---------------- PTX helpers (all family-stable, no 'a' features) ----------------
__device__ __forceinline__ uint32_t smem_u32(const void* p) {
    uint32_t a;
    asm("{ .reg .u64 t; cvta.to.shared.u64 t, %1; cvt.u32.u64 %0, t; }" : "=r"(a) : "l"(p));
    return a;
}
__device__ __forceinline__ void cpa16(uint32_t s, const void* g) {
    asm volatile("cp.async.cg.shared.global [%0], [%1], 16;" :: "r"(s), "l"(g));
}
__device__ __forceinline__ void ldm4(uint32_t* r, uint32_t addr) {
    asm volatile("ldmatrix.sync.aligned.m8n8.x4.shared.b16 {%0,%1,%2,%3}, [%4];"
                 : "=r"(r[0]), "=r"(r[1]), "=r"(r[2]), "=r"(r[3]) : "r"(addr));
}
__device__ __forceinline__ void mma_bf16(float* c, const uint32_t* a, uint32_t b0, uint32_t b1) {
    asm volatile(
        "mma.sync.aligned.m16n8k16.row.col.f32.bf16.bf16.f32 "
        "{%0,%1,%2,%3}, {%4,%5,%6,%7}, {%8,%9}, {%0,%1,%2,%3};"
        : "+f"(c[0]), "+f"(c[1]), "+f"(c[2]), "+f"(c[3])
        : "r"(a[0]), "r"(a[1]), "r"(a[2]), "r"(a[3]), "r"(b0), "r"(b1));
}
__device__ __forceinline__ float tanh_apx(float x) {
    float y;
    asm("tanh.approx.f32 %0, %1;" : "=f"(y) : "f"(x));
    return y;
}
#define SWZ(o) ((o) ^ (((o) >> 3) & 0x70))

// ---------------- prepass kernels ----------------
__global__ void conv_a_kernel(const float* __restrict__ x) {
    size_t i = (size_t)blockIdx.x * blockDim.x + threadIdx.x;  // over 4.19M float4
    float4 v = ((const float4*)x)[i];
    __nv_bfloat16 h0 = __float2bfloat16(v.x), h1 = __float2bfloat16(v.y);
    __nv_bfloat16 h2 = __float2bfloat16(v.z), h3 = __float2bfloat16(v.w);
    __nv_bfloat16 l0 = __float2bfloat16(v.x - __bfloat162float(h0));
    __nv_bfloat16 l1 = __float2bfloat16(v.y - __bfloat162float(h1));
    __nv_bfloat16 l2 = __float2bfloat16(v.z - __bfloat162float(h2));
    __nv_bfloat16 l3 = __float2bfloat16(v.w - __bfloat162float(h3));
    __nv_bfloat162* Ah = (__nv_bfloat162*)g_A2;
    __nv_bfloat162* Al = (__nv_bfloat162*)(g_A2 + (size_t)BATCH * IN_DIM);
    __nv_bfloat162 p;
    p.x = h0; p.y = h1; Ah[i * 2 + 0] = p;
    p.x = h2; p.y = h3; Ah[i * 2 + 1] = p;
    p.x = l0; p.y = l1; Al[i * 2 + 0] = p;
    p.x = l2; p.y = l3; Al[i * 2 + 1] = p;
}

__global__ void conv_w_kernel(const float* __restrict__ W) {  // W:[IN_DIM][OUT_DIM] -> W^T hi/lo
    __shared__ float t[32][33];
    int bx = blockIdx.x * 32, by = blockIdx.y * 32;
    int tx = threadIdx.x, ty = threadIdx.y;
#pragma unroll
    for (int j = 0; j < 32; j += 8)
        t[ty + j][tx] = W[(size_t)(by + ty + j) * OUT_DIM + bx + tx];
    __syncthreads();
#pragma unroll
    for (int j = 0; j < 32; j += 8) {
        float v = t[tx][ty + j];                 // = W[by+tx][bx+ty+j]
        size_t n = bx + ty + j, k = by + tx;
        __nv_bfloat16 h = __float2bfloat16(v);
        __nv_bfloat16 l = __float2bfloat16(v - __bfloat162float(h));
        g_W2[n * IN_DIM + k] = h;
        g_W2[(OUT_DIM + n) * IN_DIM + k] = l;
    }
}

__global__ void hd_bias_kernel(const float* __restrict__ hdw, const float* __restrict__ bias) {
    int o = blockIdx.x * blockDim.x + threadIdx.x;
    if (o < OUT_DIM) {
        float p = 1.0f;
#pragma unroll
        for (int d = 0; d < DEPTH; ++d)
            p *= cosf(hdw[(size_t)d * IN_DIM * OUT_DIM + (size_t)o * OUT_DIM]);
        g_add[o] = bias[o] + p * p * (1.0f / (float)IN_DIM);
    }
}

// ---------------- mma.sync GEMM ----------------
// CTA tile M=128 x N=256, K-chunk=64 (rows of 128B, SW128), K'=6144 -> 96 chunks.
// 8 warps (2m x 4n), warp tile 64x64. 3-stage cp.async pipeline.
#define A_BYTES  (128 * 128)                     // 16 KB
#define B_BYTES  (256 * 128)                     // 32 KB
#define STG_B    (A_BYTES + B_BYTES)             // 48 KB
#define NCHUNK   96
#define NSTAGE   3

__device__ __forceinline__ void load_chunk(int c, uint32_t sb, int tid, int m0, int n0) {
    int seg = c >> 5;                    // 0: hi*hi, 1: hi*lo, 2: lo*hi
    int kb  = (c & 31) << 6;
    size_t arow = (seg == 2 ? (size_t)BATCH : 0) + m0;
    size_t brow = (seg == 1 ? (size_t)OUT_DIM : 0) + n0;
    const __nv_bfloat16* Ag = g_A2 + arow * IN_DIM + kb;
    const __nv_bfloat16* Bg = g_W2 + brow * IN_DIM + kb;
#pragma unroll
    for (int t = 0; t < 12; ++t) {
        int idx = tid + t * 256;
        if (idx < 1024) {                               // A: 1024 x 16B
            int r = idx >> 3, c16 = idx & 7;
            cpa16(sb + SWZ(r * 128 + c16 * 16), Ag + (size_t)r * IN_DIM + c16 * 8);
        } else {                                        // B: 2048 x 16B
            int j = idx - 1024;
            int r = j >> 3, c16 = j & 7;
            cpa16(sb + A_BYTES + SWZ(r * 128 + c16 * 16), Bg + (size_t)r * IN_DIM + c16 * 8);
        }
    }
}

__global__ __launch_bounds__(256, 1) void gemm_mma_kernel(float* __restrict__ C) {
    extern __shared__ char smem_raw[];
    const uint32_t s0 = (smem_u32(smem_raw) + 1023u) & ~1023u;
    const int tid = threadIdx.x;
    const int wid = tid >> 5, lane = tid & 31;
    const int warp_m = wid & 1, warp_n = wid >> 1;     // 2 x 4
    const int m0 = blockIdx.y * 128;
    const int n0 = blockIdx.x * 256;

    // per-lane ldmatrix address precompute (row*128 and xor pattern)
    const int lrow = lane & 7;
    const int lt = lane >> 3;                          // 0..3 -> tile order (m,k),(m+8,k),(m,k+8),(m+8,k+8)
    uint32_t a_off[4], a_xo[4], b_off[4], b_xo[4];
#pragma unroll
    for (int i = 0; i < 4; ++i) {
        int ra = warp_m * 64 + i * 16 + (lt & 1) * 8 + lrow;
        a_off[i] = ra * 128; a_xo[i] = (ra & 7) * 16;
        int rb = warp_n * 64 + i * 16 + (lt & 1) * 8 + lrow;
        b_off[i] = rb * 128; b_xo[i] = (rb & 7) * 16;
    }
    const uint32_t kbase = (lt >> 1) * 16;             // 16B half-select within k16

    float acc[4][8][4];
#pragma unroll
    for (int i = 0; i < 4; ++i)
#pragma unroll
        for (int j = 0; j < 8; ++j)
#pragma unroll
            for (int q = 0; q < 4; ++q) acc[i][j][q] = 0.0f;

    // prologue: fill 3 stages
#pragma unroll
    for (int s = 0; s < NSTAGE; ++s) {
        load_chunk(s, s0 + s * STG_B, tid, m0, n0);
        asm volatile("cp.async.commit_group;" ::: "memory");
    }

    for (int c = 0; c < NCHUNK; ++c) {
        asm volatile("cp.async.wait_group %0;" :: "n"(NSTAGE - 1) : "memory");
        __syncthreads();

        const uint32_t sb = s0 + (c % NSTAGE) * STG_B;
        const uint32_t Asb = sb, Bsb = sb + A_BYTES;
#pragma unroll
        for (int ks = 0; ks < 4; ++ks) {
            const uint32_t kof = ks * 32 + kbase;
            uint32_t af[4][4], bf[4][4];
#pragma unroll
            for (int mt = 0; mt < 4; ++mt)
                ldm4(af[mt], Asb + a_off[mt] + (kof ^ a_xo[mt]));
#pragma unroll
            for (int np = 0; np < 4; ++np)
                ldm4(bf[np], Bsb + b_off[np] + (kof ^ b_xo[np]));
#pragma unroll
            for (int mt = 0; mt < 4; ++mt)
#pragma unroll
                for (int np = 0; np < 4; ++np) {
                    mma_bf16(acc[mt][2 * np + 0], af[mt], bf[np][0], bf[np][2]);
                    mma_bf16(acc[mt][2 * np + 1], af[mt], bf[np][1], bf[np][3]);
                }
        }
        __syncthreads();
        if (c + NSTAGE < NCHUNK) load_chunk(c + NSTAGE, sb, tid, m0, n0);
        asm volatile("cp.async.commit_group;" ::: "memory");   // empty group near tail keeps counts aligned
    }

    // ---- epilogue: out = tanh(acc + bias + hd), direct fragment stores ----
    const int g = lane >> 2, tig = lane & 3;
#pragma unroll
    for (int mt = 0; mt < 4; ++mt) {
        const int r0 = m0 + warp_m * 64 + mt * 16 + g;
#pragma unroll
        for (int nt = 0; nt < 8; ++nt) {
            const int col = n0 + warp_n * 64 + nt * 8 + tig * 2;
            const float a0 = __ldg(&g_add[col]);
            const float a1 = __ldg(&g_add[col + 1]);
            float2 o0, o1;
            o0.x = tanh_apx(acc[mt][nt][0] + a0);
            o0.y = tanh_apx(acc[mt][nt][1] + a1);
            o1.x = tanh_apx(acc[mt][nt][2] + a0);
            o1.y = tanh_apx(acc[mt][nt][3] + a1);
            *(float2*)(C + (size_t)r0 * OUT_DIM + col) = o0;
            *(float2*)(C + (size_t)(r0 + 8) * OUT_DIM + col) = o1;
        }
    }
}

// ---------------- launch ----------------
#define GEMM_SMEM (NSTAGE * STG_B + 1024)

extern "C" void kernel_launch(void* const* d_in, const int* in_sizes, int n_in,
                              void* d_out, int out_size) {
    const float* x   = (const float*)d_in[0];  // [8192, 2048]
    const float* hdw = (const float*)d_in[1];  // [5, 2048, 2048]
    const float* W   = (const float*)d_in[2];  // [2048, 2048]
    const float* b   = (const float*)d_in[3];  // [2048]
    float* out = (float*)d_out;                // [8192, 2048]

    cudaFuncSetAttribute(gemm_mma_kernel, cudaFuncAttributeMaxDynamicSharedMemorySize, GEMM_SMEM);

    conv_a_kernel<<<(BATCH * IN_DIM / 4) / 256, 256>>>(x);
    conv_w_kernel<<<dim3(OUT_DIM / 32, IN_DIM / 32), dim3(32, 8)>>>(W);
    hd_bias_kernel<<<OUT_DIM / 256, 256>>>(hdw, b);

    dim3 grid(OUT_DIM / 256, BATCH / 128);     // (8, 64)
    gemm_mma_kernel<<<grid, 256, GEMM_SMEM>>>(out);
}

// round 6
// speedup vs baseline: 1.9530x; 1.0038x over previous
#include <cuda_runtime.h>
#include <cuda_bf16.h>
#include <stdint.h>

#define BATCH   8192
#define IN_DIM  2048
#define OUT_DIM 2048
#define DEPTH   5

// ---------------- device scratch (no allocs allowed) ----------------
__device__ __nv_bfloat16 g_A2[(size_t)2 * BATCH * IN_DIM];    // rows 0..8191 = hi(x), 8192.. = lo(x)
__device__ __nv_bfloat16 g_W2[(size_t)2 * OUT_DIM * IN_DIM];  // rows n = hi(W^T), 2048+n = lo(W^T)
__device__ float g_add[OUT_DIM];                              // bias + hd

// ---------------- PTX helpers (family-stable only) ----------------
__device__ __forceinline__ uint32_t smem_u32(const void* p) {
    uint32_t a;
    asm("{ .reg .u64 t; cvta.to.shared.u64 t, %1; cvt.u32.u64 %0, t; }" : "=r"(a) : "l"(p));
    return a;
}
__device__ __forceinline__ void cpa16(uint32_t s, const void* g) {
    asm volatile("cp.async.cg.shared.global [%0], [%1], 16;" :: "r"(s), "l"(g));
}
__device__ __forceinline__ void ldm4(uint32_t* r, uint32_t addr) {
    asm volatile("ldmatrix.sync.aligned.m8n8.x4.shared.b16 {%0,%1,%2,%3}, [%4];"
                 : "=r"(r[0]), "=r"(r[1]), "=r"(r[2]), "=r"(r[3]) : "r"(addr));
}
__device__ __forceinline__ void mma_bf16(float* c, const uint32_t* a, uint32_t b0, uint32_t b1) {
    asm volatile(
        "mma.sync.aligned.m16n8k16.row.col.f32.bf16.bf16.f32 "
        "{%0,%1,%2,%3}, {%4,%5,%6,%7}, {%8,%9}, {%0,%1,%2,%3};"
        : "+f"(c[0]), "+f"(c[1]), "+f"(c[2]), "+f"(c[3])
        : "r"(a[0]), "r"(a[1]), "r"(a[2]), "r"(a[3]), "r"(b0), "r"(b1));
}
__device__ __forceinline__ float tanh_apx(float x) {
    float y;
    asm("tanh.approx.f32 %0, %1;" : "=f"(y) : "f"(x));
    return y;
}
#define SWZ(o) ((o) ^ (((o) >> 3) & 0x70))

// ---------------- prepass kernels ----------------
__global__ void conv_a_kernel(const float* __restrict__ x) {
    size_t i = (size_t)blockIdx.x * blockDim.x + threadIdx.x;  // over 4.19M float4
    float4 v = ((const float4*)x)[i];
    __nv_bfloat16 h0 = __float2bfloat16(v.x), h1 = __float2bfloat16(v.y);
    __nv_bfloat16 h2 = __float2bfloat16(v.z), h3 = __float2bfloat16(v.w);
    __nv_bfloat16 l0 = __float2bfloat16(v.x - __bfloat162float(h0));
    __nv_bfloat16 l1 = __float2bfloat16(v.y - __bfloat162float(h1));
    __nv_bfloat16 l2 = __float2bfloat16(v.z - __bfloat162float(h2));
    __nv_bfloat16 l3 = __float2bfloat16(v.w - __bfloat162float(h3));
    __nv_bfloat162* Ah = (__nv_bfloat162*)g_A2;
    __nv_bfloat162* Al = (__nv_bfloat162*)(g_A2 + (size_t)BATCH * IN_DIM);
    __nv_bfloat162 p;
    p.x = h0; p.y = h1; Ah[i * 2 + 0] = p;
    p.x = h2; p.y = h3; Ah[i * 2 + 1] = p;
    p.x = l0; p.y = l1; Al[i * 2 + 0] = p;
    p.x = l2; p.y = l3; Al[i * 2 + 1] = p;
}

__global__ void conv_w_kernel(const float* __restrict__ W) {  // W:[IN_DIM][OUT_DIM] -> W^T hi/lo
    __shared__ float t[32][33];
    int bx = blockIdx.x * 32, by = blockIdx.y * 32;
    int tx = threadIdx.x, ty = threadIdx.y;
#pragma unroll
    for (int j = 0; j < 32; j += 8)
        t[ty + j][tx] = W[(size_t)(by + ty + j) * OUT_DIM + bx + tx];
    __syncthreads();
#pragma unroll
    for (int j = 0; j < 32; j += 8) {
        float v = t[tx][ty + j];                 // = W[by+tx][bx+ty+j]
        size_t n = bx + ty + j, k = by + tx;
        __nv_bfloat16 h = __float2bfloat16(v);
        __nv_bfloat16 l = __float2bfloat16(v - __bfloat162float(h));
        g_W2[n * IN_DIM + k] = h;
        g_W2[(OUT_DIM + n) * IN_DIM + k] = l;
    }
}

__global__ void hd_bias_kernel(const float* __restrict__ hdw, const float* __restrict__ bias) {
    int o = blockIdx.x * blockDim.x + threadIdx.x;
    if (o < OUT_DIM) {
        float p = 1.0f;
#pragma unroll
        for (int d = 0; d < DEPTH; ++d)
            p *= cosf(hdw[(size_t)d * IN_DIM * OUT_DIM + (size_t)o * OUT_DIM]);
        g_add[o] = bias[o] + p * p * (1.0f / (float)IN_DIM);
    }
}

// ---------------- mma.sync GEMM ----------------
// CTA tile M=128 x N=256, K-chunk=64 (rows of 128B, SW128), K'=6144 -> 96 chunks.
// 8 warps (2m x 4n), warp tile 64x64. 4-stage cp.async pipeline; loads for
// chunk c+3 are issued BEFORE compute of chunk c (dest buffer freed at c-1),
// so global latency + LDGSTS issue hide under the MMA stream. One sync/chunk.
#define A_BYTES  (128 * 128)                     // 16 KB
#define B_BYTES  (256 * 128)                     // 32 KB
#define STG_B    (A_BYTES + B_BYTES)             // 48 KB
#define NCHUNK   96
#define NSTAGE   4

__device__ __forceinline__ void load_chunk(int c, uint32_t sb, int tid, int m0, int n0) {
    int seg = c >> 5;                    // 0: hi*hi, 1: hi*lo, 2: lo*hi
    int kb  = (c & 31) << 6;
    size_t arow = (seg == 2 ? (size_t)BATCH : 0) + m0;
    size_t brow = (seg == 1 ? (size_t)OUT_DIM : 0) + n0;
    const __nv_bfloat16* Ag = g_A2 + arow * IN_DIM + kb;
    const __nv_bfloat16* Bg = g_W2 + brow * IN_DIM + kb;
#pragma unroll
    for (int t = 0; t < 12; ++t) {
        int idx = tid + t * 256;
        if (idx < 1024) {                               // A: 1024 x 16B
            int r = idx >> 3, c16 = idx & 7;
            cpa16(sb + SWZ(r * 128 + c16 * 16), Ag + (size_t)r * IN_DIM + c16 * 8);
        } else {                                        // B: 2048 x 16B
            int j = idx - 1024;
            int r = j >> 3, c16 = j & 7;
            cpa16(sb + A_BYTES + SWZ(r * 128 + c16 * 16), Bg + (size_t)r * IN_DIM + c16 * 8);
        }
    }
}

__global__ __launch_bounds__(256, 1) void gemm_mma_kernel(float* __restrict__ C) {
    extern __shared__ char smem_raw[];
    const uint32_t s0 = (smem_u32(smem_raw) + 1023u) & ~1023u;
    const int tid = threadIdx.x;
    const int wid = tid >> 5, lane = tid & 31;
    const int warp_m = wid & 1, warp_n = wid >> 1;     // 2 x 4
    const int m0 = blockIdx.y * 128;
    const int n0 = blockIdx.x * 256;

    // XOR-folded ldmatrix addressing: kof (= ks*32 + kbase) lives in bits 4-6,
    // the swizzle xor pattern lives in bits 4-6, row offsets in bits >= 7.
    // So addr = base + (pre ^ kof) with pre = row_off | xor_pat.
    const int lrow = lane & 7;
    const int lt = lane >> 3;                          // fragment tile order
    uint32_t a_pre[4], b_pre[4];
#pragma unroll
    for (int i = 0; i < 4; ++i) {
        int ra = warp_m * 64 + i * 16 + (lt & 1) * 8 + lrow;
        a_pre[i] = (uint32_t)(ra * 128) | (uint32_t)((ra & 7) * 16);
        int rb = warp_n * 64 + i * 16 + (lt & 1) * 8 + lrow;
        b_pre[i] = (uint32_t)(rb * 128) | (uint32_t)((rb & 7) * 16);
    }
    const uint32_t kbase = (lt >> 1) * 16;             // 16B half-select within k16

    float acc[4][8][4];
#pragma unroll
    for (int i = 0; i < 4; ++i)
#pragma unroll
        for (int j = 0; j < 8; ++j)
#pragma unroll
            for (int q = 0; q < 4; ++q) acc[i][j][q] = 0.0f;

    // prologue: fill first 3 of 4 stages
#pragma unroll
    for (int s = 0; s < NSTAGE - 1; ++s) {
        load_chunk(s, s0 + s * STG_B, tid, m0, n0);
        asm volatile("cp.async.commit_group;" ::: "memory");
    }

    for (int c = 0; c < NCHUNK; ++c) {
        asm volatile("cp.async.wait_group %0;" :: "n"(NSTAGE - 2) : "memory");
        __syncthreads();

        // issue loads for chunk c+3 into buffer (c+3)%4 (freed by compute of c-1,
        // which all warps completed before the sync above)
        if (c + NSTAGE - 1 < NCHUNK)
            load_chunk(c + NSTAGE - 1, s0 + ((c + NSTAGE - 1) & (NSTAGE - 1)) * STG_B,
                       tid, m0, n0);
        asm volatile("cp.async.commit_group;" ::: "memory");

        const uint32_t sb = s0 + (c & (NSTAGE - 1)) * STG_B;
        const uint32_t Asb = sb, Bsb = sb + A_BYTES;
#pragma unroll
        for (int ks = 0; ks < 4; ++ks) {
            const uint32_t kof = ks * 32 + kbase;
            uint32_t af[4][4], bf[4][4];
#pragma unroll
            for (int mt = 0; mt < 4; ++mt)
                ldm4(af[mt], Asb + (a_pre[mt] ^ kof));
#pragma unroll
            for (int np = 0; np < 4; ++np)
                ldm4(bf[np], Bsb + (b_pre[np] ^ kof));
#pragma unroll
            for (int mt = 0; mt < 4; ++mt)
#pragma unroll
                for (int np = 0; np < 4; ++np) {
                    mma_bf16(acc[mt][2 * np + 0], af[mt], bf[np][0], bf[np][2]);
                    mma_bf16(acc[mt][2 * np + 1], af[mt], bf[np][1], bf[np][3]);
                }
        }
    }

    // ---- epilogue: out = tanh(acc + bias + hd), direct fragment stores ----
    const int g = lane >> 2, tig = lane & 3;
#pragma unroll
    for (int mt = 0; mt < 4; ++mt) {
        const int r0 = m0 + warp_m * 64 + mt * 16 + g;
#pragma unroll
        for (int nt = 0; nt < 8; ++nt) {
            const int col = n0 + warp_n * 64 + nt * 8 + tig * 2;
            const float a0 = __ldg(&g_add[col]);
            const float a1 = __ldg(&g_add[col + 1]);
            float2 o0, o1;
            o0.x = tanh_apx(acc[mt][nt][0] + a0);
            o0.y = tanh_apx(acc[mt][nt][1] + a1);
            o1.x = tanh_apx(acc[mt][nt][2] + a0);
            o1.y = tanh_apx(acc[mt][nt][3] + a1);
            *(float2*)(C + (size_t)r0 * OUT_DIM + col) = o0;
            *(float2*)(C + (size_t)(r0 + 8) * OUT_DIM + col) = o1;
        }
    }
}

// ---------------- launch ----------------
#define GEMM_SMEM (NSTAGE * STG_B + 1024)

extern "C" void kernel_launch(void* const* d_in, const int* in_sizes, int n_in,
                              void* d_out, int out_size) {
    const float* x   = (const float*)d_in[0];  // [8192, 2048]
    const float* hdw = (const float*)d_in[1];  // [5, 2048, 2048]
    const float* W   = (const float*)d_in[2];  // [2048, 2048]
    const float* b   = (const float*)d_in[3];  // [2048]
    float* out = (float*)d_out;                // [8192, 2048]

    cudaFuncSetAttribute(gemm_mma_kernel, cudaFuncAttributeMaxDynamicSharedMemorySize, GEMM_SMEM);

    conv_a_kernel<<<(BATCH * IN_DIM / 4) / 256, 256>>>(x);
    conv_w_kernel<<<dim3(OUT_DIM / 32, IN_DIM / 32), dim3(32, 8)>>>(W);
    hd_bias_kernel<<<OUT_DIM / 256, 256>>>(hdw, b);

    dim3 grid(OUT_DIM / 256, BATCH / 128);     // (8, 64)
    gemm_mma_kernel<<<grid, 256, GEMM_SMEM>>>(out);
}

// round 8
// speedup vs baseline: 2.4131x; 1.2356x over previous
#include <cuda_runtime.h>
#include <cuda_bf16.h>
#include <stdint.h>

#define BATCH   8192
#define IN_DIM  2048
#define OUT_DIM 2048
#define DEPTH   5

// ---------------- device scratch (no allocs allowed) ----------------
__device__ __nv_bfloat16 g_A2[(size_t)2 * BATCH * IN_DIM];    // rows 0..8191 = hi(x), 8192.. = lo(x)
__device__ __nv_bfloat16 g_W2[(size_t)2 * OUT_DIM * IN_DIM];  // rows n = hi(W^T), 2048+n = lo(W^T)
__device__ float g_add[OUT_DIM];                              // bias + hd

// ---------------- PTX helpers (family-stable only) ----------------
__device__ __forceinline__ uint32_t smem_u32(const void* p) {
    uint32_t a;
    asm("{ .reg .u64 t; cvta.to.shared.u64 t, %1; cvt.u32.u64 %0, t; }" : "=r"(a) : "l"(p));
    return a;
}
__device__ __forceinline__ void cpa16(uint32_t s, const void* g) {
    asm volatile("cp.async.cg.shared.global [%0], [%1], 16;" :: "r"(s), "l"(g));
}
__device__ __forceinline__ void ldm4(uint32_t* r, uint32_t addr) {
    asm volatile("ldmatrix.sync.aligned.m8n8.x4.shared.b16 {%0,%1,%2,%3}, [%4];"
                 : "=r"(r[0]), "=r"(r[1]), "=r"(r[2]), "=r"(r[3]) : "r"(addr));
}
__device__ __forceinline__ void mma_bf16(float* c, const uint32_t* a, uint32_t b0, uint32_t b1) {
    asm volatile(
        "mma.sync.aligned.m16n8k16.row.col.f32.bf16.bf16.f32 "
        "{%0,%1,%2,%3}, {%4,%5,%6,%7}, {%8,%9}, {%0,%1,%2,%3};"
        : "+f"(c[0]), "+f"(c[1]), "+f"(c[2]), "+f"(c[3])
        : "r"(a[0]), "r"(a[1]), "r"(a[2]), "r"(a[3]), "r"(b0), "r"(b1));
}
__device__ __forceinline__ float tanh_apx(float x) {
    float y;
    asm("tanh.approx.f32 %0, %1;" : "=f"(y) : "f"(x));
    return y;
}
#define SWZ(o) ((o) ^ (((o) >> 3) & 0x70))

// ---------------- prepass kernels ----------------
__global__ void conv_a_kernel(const float* __restrict__ x) {
    size_t i = (size_t)blockIdx.x * blockDim.x + threadIdx.x;  // over 4.19M float4
    float4 v = ((const float4*)x)[i];
    __nv_bfloat16 h0 = __float2bfloat16(v.x), h1 = __float2bfloat16(v.y);
    __nv_bfloat16 h2 = __float2bfloat16(v.z), h3 = __float2bfloat16(v.w);
    __nv_bfloat16 l0 = __float2bfloat16(v.x - __bfloat162float(h0));
    __nv_bfloat16 l1 = __float2bfloat16(v.y - __bfloat162float(h1));
    __nv_bfloat16 l2 = __float2bfloat16(v.z - __bfloat162float(h2));
    __nv_bfloat16 l3 = __float2bfloat16(v.w - __bfloat162float(h3));
    __nv_bfloat162* Ah = (__nv_bfloat162*)g_A2;
    __nv_bfloat162* Al = (__nv_bfloat162*)(g_A2 + (size_t)BATCH * IN_DIM);
    __nv_bfloat162 p;
    p.x = h0; p.y = h1; Ah[i * 2 + 0] = p;
    p.x = h2; p.y = h3; Ah[i * 2 + 1] = p;
    p.x = l0; p.y = l1; Al[i * 2 + 0] = p;
    p.x = l2; p.y = l3; Al[i * 2 + 1] = p;
}

__global__ void conv_w_kernel(const float* __restrict__ W) {  // W:[IN_DIM][OUT_DIM] -> W^T hi/lo
    __shared__ float t[32][33];
    int bx = blockIdx.x * 32, by = blockIdx.y * 32;
    int tx = threadIdx.x, ty = threadIdx.y;
#pragma unroll
    for (int j = 0; j < 32; j += 8)
        t[ty + j][tx] = W[(size_t)(by + ty + j) * OUT_DIM + bx + tx];
    __syncthreads();
#pragma unroll
    for (int j = 0; j < 32; j += 8) {
        float v = t[tx][ty + j];                 // = W[by+tx][bx+ty+j]
        size_t n = bx + ty + j, k = by + tx;
        __nv_bfloat16 h = __float2bfloat16(v);
        __nv_bfloat16 l = __float2bfloat16(v - __bfloat162float(h));
        g_W2[n * IN_DIM + k] = h;
        g_W2[(OUT_DIM + n) * IN_DIM + k] = l;
    }
}

__global__ void hd_bias_kernel(const float* __restrict__ hdw, const float* __restrict__ bias) {
    int o = blockIdx.x * blockDim.x + threadIdx.x;
    if (o < OUT_DIM) {
        float p = 1.0f;
#pragma unroll
        for (int d = 0; d < DEPTH; ++d)
            p *= cosf(hdw[(size_t)d * IN_DIM * OUT_DIM + (size_t)o * OUT_DIM]);
        g_add[o] = bias[o] + p * p * (1.0f / (float)IN_DIM);
    }
}

// ---------------- mma.sync GEMM ----------------
// CTA tile M=128 x N=256, K-chunk=64, K'=6144 -> 96 chunks. 8 warps (2m x 4n),
// warp tile 64x64. 4-stage cp.async pipeline + REGISTER fragment double-buffer:
// ldmatrix for k-step ks+1 (or chunk c+1, ks=0) overlaps the HMMAs of ks, so the
// smem crossbar and the tensor pipe run concurrently instead of alternating.
#define A_BYTES  (128 * 128)                     // 16 KB
#define B_BYTES  (256 * 128)                     // 32 KB
#define STG_B    (A_BYTES + B_BYTES)             // 48 KB
#define NCHUNK   96
#define NSTAGE   4

__device__ __forceinline__ void load_chunk(int c, uint32_t sb, int tid, int m0, int n0) {
    int seg = c >> 5;                    // 0: hi*hi, 1: hi*lo, 2: lo*hi
    int kb  = (c & 31) << 6;
    size_t arow = (seg == 2 ? (size_t)BATCH : 0) + m0;
    size_t brow = (seg == 1 ? (size_t)OUT_DIM : 0) + n0;
    const __nv_bfloat16* Ag = g_A2 + arow * IN_DIM + kb;
    const __nv_bfloat16* Bg = g_W2 + brow * IN_DIM + kb;
#pragma unroll
    for (int t = 0; t < 12; ++t) {
        int idx = tid + t * 256;
        if (idx < 1024) {                               // A: 1024 x 16B
            int r = idx >> 3, c16 = idx & 7;
            cpa16(sb + SWZ(r * 128 + c16 * 16), Ag + (size_t)r * IN_DIM + c16 * 8);
        } else {                                        // B: 2048 x 16B
            int j = idx - 1024;
            int r = j >> 3, c16 = j & 7;
            cpa16(sb + A_BYTES + SWZ(r * 128 + c16 * 16), Bg + (size_t)r * IN_DIM + c16 * 8);
        }
    }
}

__global__ __launch_bounds__(256, 1) void gemm_mma_kernel(float* __restrict__ C) {
    extern __shared__ char smem_raw[];
    const uint32_t s0 = (smem_u32(smem_raw) + 1023u) & ~1023u;
    const int tid = threadIdx.x;
    const int wid = tid >> 5, lane = tid & 31;
    const int warp_m = wid & 1, warp_n = wid >> 1;     // 2 x 4
    const int m0 = blockIdx.y * 128;
    const int n0 = blockIdx.x * 256;

    // Swizzle xor pattern depends only on lane&7 (identical for all 4 row-tiles),
    // and row-tiles differ by a constant +2048 B -> single base per operand,
    // +i*2048 folds into LDSM immediates.
    const int lrow = lane & 7;
    const int lt = lane >> 3;
    const uint32_t xo = (uint32_t)(lrow * 16);
    const int ra0 = warp_m * 64 + (lt & 1) * 8 + lrow;
    const int rb0 = warp_n * 64 + (lt & 1) * 8 + lrow;
    const uint32_t a_pre0 = (uint32_t)(ra0 * 128) | xo;
    const uint32_t b_pre0 = (uint32_t)(rb0 * 128) | xo;
    const uint32_t kbase = (lt >> 1) * 16;             // 16B half-select within k16

    float acc[4][8][4];
#pragma unroll
    for (int i = 0; i < 4; ++i)
#pragma unroll
        for (int j = 0; j < 8; ++j)
#pragma unroll
            for (int q = 0; q < 4; ++q) acc[i][j][q] = 0.0f;

    uint32_t af[2][4][4], bf[2][4][4];

#define LD_FRAGS(B, Asb_, Bsb_, kof_) do {                          \
        const uint32_t _ax = (Asb_) + (a_pre0 ^ (uint32_t)(kof_));  \
        const uint32_t _bx = (Bsb_) + (b_pre0 ^ (uint32_t)(kof_));  \
        ldm4(af[B][0], _ax);                                        \
        ldm4(af[B][1], _ax + 2048);                                 \
        ldm4(af[B][2], _ax + 4096);                                 \
        ldm4(af[B][3], _ax + 6144);                                 \
        ldm4(bf[B][0], _bx);                                        \
        ldm4(bf[B][1], _bx + 2048);                                 \
        ldm4(bf[B][2], _bx + 4096);                                 \
        ldm4(bf[B][3], _bx + 6144);                                 \
    } while (0)

#define DO_MMA(B) do {                                                  \
        _Pragma("unroll")                                               \
        for (int mt = 0; mt < 4; ++mt)                                  \
            _Pragma("unroll")                                           \
            for (int np = 0; np < 4; ++np) {                            \
                mma_bf16(acc[mt][2 * np + 0], af[B][mt], bf[B][np][0], bf[B][np][2]); \
                mma_bf16(acc[mt][2 * np + 1], af[B][mt], bf[B][np][1], bf[B][np][3]); \
            }                                                           \
    } while (0)

    // prologue: fill first 3 of 4 stages
#pragma unroll
    for (int s = 0; s < NSTAGE - 1; ++s) {
        load_chunk(s, s0 + s * STG_B, tid, m0, n0);
        asm volatile("cp.async.commit_group;" ::: "memory");
    }
    // preamble: chunk 0 ready -> preload its ks=0 fragments into buffer 0
    asm volatile("cp.async.wait_group 2;" ::: "memory");
    __syncthreads();
    LD_FRAGS(0, s0, s0 + A_BYTES, kbase);

    for (int c = 0; c < NCHUNK; ++c) {
        // chunks <= c+1 complete after this (needed for the cross-chunk prefetch)
        asm volatile("cp.async.wait_group 1;" ::: "memory");
        __syncthreads();

        // global loads for chunk c+3 into its buffer (freed by compute of c-1)
        if (c + NSTAGE - 1 < NCHUNK)
            load_chunk(c + NSTAGE - 1, s0 + ((c + NSTAGE - 1) & (NSTAGE - 1)) * STG_B,
                       tid, m0, n0);
        asm volatile("cp.async.commit_group;" ::: "memory");

        const uint32_t sb = s0 + (c & (NSTAGE - 1)) * STG_B;
        const uint32_t Asb = sb, Bsb = sb + A_BYTES;

#pragma unroll
        for (int ks = 0; ks < 4; ++ks) {
            const int cb = ks & 1;
            if (ks < 3) {
                LD_FRAGS(cb ^ 1, Asb, Bsb, (ks + 1) * 32 + kbase);
            } else if (c + 1 < NCHUNK) {
                // prefetch ks=0 of chunk c+1 (its cp.async group completed at
                // this iteration's wait_group 1; the buffer's next overwrite is
                // ordered behind the next __syncthreads)
                const uint32_t sbn = s0 + ((c + 1) & (NSTAGE - 1)) * STG_B;
                LD_FRAGS(cb ^ 1, sbn, sbn + A_BYTES, kbase);
            }
            DO_MMA(cb);
        }
    }

    // ---- epilogue: out = tanh(acc + bias + hd), direct fragment stores ----
    const int g = lane >> 2, tig = lane & 3;
#pragma unroll
    for (int mt = 0; mt < 4; ++mt) {
        const int r0 = m0 + warp_m * 64 + mt * 16 + g;
#pragma unroll
        for (int nt = 0; nt < 8; ++nt) {
            const int col = n0 + warp_n * 64 + nt * 8 + tig * 2;
            const float a0 = __ldg(&g_add[col]);
            const float a1 = __ldg(&g_add[col + 1]);
            float2 o0, o1;
            o0.x = tanh_apx(acc[mt][nt][0] + a0);
            o0.y = tanh_apx(acc[mt][nt][1] + a1);
            o1.x = tanh_apx(acc[mt][nt][2] + a0);
            o1.y = tanh_apx(acc[mt][nt][3] + a1);
            *(float2*)(C + (size_t)r0 * OUT_DIM + col) = o0;
            *(float2*)(C + (size_t)(r0 + 8) * OUT_DIM + col) = o1;
        }
    }
}

// ---------------- launch ----------------
#define GEMM_SMEM (NSTAGE * STG_B + 1024)

extern "C" void kernel_launch(void* const* d_in, const int* in_sizes, int n_in,
                              void* d_out, int out_size) {
    const float* x   = (const float*)d_in[0];  // [8192, 2048]
    const float* hdw = (const float*)d_in[1];  // [5, 2048, 2048]
    const float* W   = (const float*)d_in[2];  // [2048, 2048]
    const float* b   = (const float*)d_in[3];  // [2048]
    float* out = (float*)d_out;                // [8192, 2048]

    cudaFuncSetAttribute(gemm_mma_kernel, cudaFuncAttributeMaxDynamicSharedMemorySize, GEMM_SMEM);

    conv_a_kernel<<<(BATCH * IN_DIM / 4) / 256, 256>>>(x);
    conv_w_kernel<<<dim3(OUT_DIM / 32, IN_DIM / 32), dim3(32, 8)>>>(W);
    hd_bias_kernel<<<OUT_DIM / 256, 256>>>(hdw, b);

    dim3 grid(OUT_DIM / 256, BATCH / 128);     // (8, 64)
    gemm_mma_kernel<<<grid, 256, GEMM_SMEM>>>(out);
}